// round 14
// baseline (speedup 1.0000x reference)
#include <cuda_runtime.h>
#include <cuda.h>
#include <math.h>
#include <stdint.h>

#define T_STEPS   64
#define ROWS      32             // rows per tile (= consumer threads)
#define CTHREADS  32             // consumer warp (warp 0)
#define THREADS   64             // + producer warp (warp 1)
#define TCH       16             // timesteps per chunk (64B per row)
#define NCHT      4              // chunks per tile
#define DEPTH     3              // ring slots; slot = k % 3
#define CH_B      (ROWS * TCH * 4)       // 2048 bytes per array per chunk
#define SLOT_B    (3 * CH_B)             // 6144: S+C+Y per slot
#define SMEM_DYN  (512 + DEPTH * SLOT_B + 64)   // ~19 KB -> 10 CTAs/SM
#define NUM_CTAS  1480           // 10 * 148 SMs
#define MAXTILES  16384

// Deterministic per-TILE ll partials + self-resetting counters.
__device__ double       g_tilell[MAXTILES];
__device__ unsigned int g_work;
__device__ unsigned int g_ticket;

// ---------------- PTX helpers ----------------
__device__ __forceinline__ void mbar_init(uint32_t a, uint32_t cnt) {
    asm volatile("mbarrier.init.shared.b64 [%0], %1;" :: "r"(a), "r"(cnt) : "memory");
}
__device__ __forceinline__ void mbar_expect(uint32_t a, uint32_t bytes) {
    asm volatile("mbarrier.arrive.expect_tx.shared.b64 _, [%0], %1;"
                 :: "r"(a), "r"(bytes) : "memory");
}
__device__ __forceinline__ void mbar_arrive(uint32_t a) {
    asm volatile("mbarrier.arrive.shared.b64 _, [%0];" :: "r"(a) : "memory");
}
__device__ __forceinline__ void mbar_wait(uint32_t a, uint32_t parity) {
    uint32_t done;
    asm volatile(
        "{\n\t.reg .pred p;\n\t"
        "mbarrier.try_wait.parity.acquire.cta.shared::cta.b64 p, [%1], %2;\n\t"
        "selp.b32 %0, 1, 0, p;\n\t}"
        : "=r"(done) : "r"(a), "r"(parity) : "memory");
    if (!done) {
        asm volatile(
            "{\n\t.reg .pred P1;\n\t"
            "W_%=:\n\t"
            "mbarrier.try_wait.parity.acquire.cta.shared::cta.b64 P1, [%0], %1, 0x989680;\n\t"
            "@P1 bra.uni D_%=;\n\t"
            "bra.uni W_%=;\n\t"
            "D_%=:\n\t}" :: "r"(a), "r"(parity) : "memory");
    }
}
__device__ __forceinline__ void tma_load2d(uint32_t dst, const CUtensorMap* m,
                                           int c0, int c1, uint32_t mb) {
    asm volatile(
        "cp.async.bulk.tensor.2d.shared::cta.global.tile.mbarrier::complete_tx::bytes "
        "[%0], [%1, {%2, %3}], [%4];"
        :: "r"(dst), "l"(m), "r"(c0), "r"(c1), "r"(mb) : "memory");
}
__device__ __forceinline__ void tma_store2d(const CUtensorMap* m, int c0, int c1,
                                            uint32_t src) {
    asm volatile(
        "cp.async.bulk.tensor.2d.global.shared::cta.tile.bulk_group "
        "[%0, {%1, %2}], [%3];"
        :: "l"(m), "r"(c0), "r"(c1), "r"(src) : "memory");
}
__device__ __forceinline__ void fence_proxy_async_cta() {
    asm volatile("fence.proxy.async.shared::cta;" ::: "memory");
}
__device__ __forceinline__ void tma_commit() {
    asm volatile("cp.async.bulk.commit_group;" ::: "memory");
}
__device__ __forceinline__ void tma_wait_read1() {
    asm volatile("cp.async.bulk.wait_group.read 1;" ::: "memory");
}
__device__ __forceinline__ void tma_wait_read0() {
    asm volatile("cp.async.bulk.wait_group.read 0;" ::: "memory");
}

__global__ __launch_bounds__(THREADS)
void hmm_filter_ws10(
    const __grid_constant__ CUtensorMap tmS,
    const __grid_constant__ CUtensorMap tmC,
    const __grid_constant__ CUtensorMap tmY,
    const __grid_constant__ CUtensorMap tmZf,
    const __grid_constant__ CUtensorMap tmZv,
    const float* __restrict__ G,   // (N,1)
    const float* __restrict__ L,   // (N,3)
    const float* __restrict__ p_psi,
    const float* __restrict__ p_gS,
    const float* __restrict__ p_gC,
    const float* __restrict__ p_gG,
    const float* __restrict__ p_gGS,
    const float* __restrict__ p_gGC,
    const float* __restrict__ p_gLw,
    const float* __restrict__ p_lsz,
    const float* __restrict__ p_b0,
    const float* __restrict__ p_bZ,
    const float* __restrict__ p_bS,
    const float* __restrict__ p_bG,
    const float* __restrict__ p_bGS,
    const float* __restrict__ p_bLw,
    float* __restrict__ out_ll,
    int N, int ntiles)
{
    extern __shared__ char dsm[];
    __shared__ int    tileSeq[8];
    __shared__ bool   is_last;

    const uint32_t sb = (uint32_t)__cvta_generic_to_shared(dsm);
    const uint32_t A  = (sb + 511u) & ~511u;     // 512B align (SW64 atom)
    char* const Ag    = dsm + (A - sb);

    // slot s: S at +0, C at +CH_B, Y at +2*CH_B within slot s*SLOT_B
    const uint32_t mbF = A + DEPTH * SLOT_B;        // full[3]
    const uint32_t mbD = mbF + 8 * DEPTH;           // done[3]

    const int tid  = threadIdx.x;
    const int lane = tid & 31;
    const int wid  = tid >> 5;
    const int bid  = blockIdx.x;
    const int grid = gridDim.x;

    if (tid == 0) {
        #pragma unroll
        for (int s = 0; s < DEPTH; s++) {
            mbar_init(mbF + 8 * s, 1);        // full: expect_tx / wake
            mbar_init(mbD + 8 * s, CTHREADS); // done: 32 consumer arrivals
        }
    }
    __syncthreads();

    // =====================================================================
    // Producer: warp 1, lane 0 (other lanes exit)
    // =====================================================================
    if (wid == 1) {
        if (lane != 0) return;

        int tCur  = bid;          // grid <= ntiles guaranteed by host
        int tNext = -1;
        int j = 0;
        int k = 0;

        // Prologue: load chunks 0,1 (slots 0,1) of first tile
        #pragma unroll
        for (int kk = 0; kk < 2; kk++) {
            const uint32_t s0 = A + kk * SLOT_B;
            mbar_expect(mbF + 8 * kk, SLOT_B);
            tma_load2d(s0 + 0 * CH_B, &tmS, kk * TCH, tCur * ROWS, mbF + 8 * kk);
            tma_load2d(s0 + 1 * CH_B, &tmC, kk * TCH, tCur * ROWS, mbF + 8 * kk);
            tma_load2d(s0 + 2 * CH_B, &tmY, kk * TCH, tCur * ROWS, mbF + 8 * kk);
        }

        #pragma unroll 1
        while (true) {
            const int h    = k & 3;
            const int slot = k % 3;

            // ---- store chunk k once compute finished it ----
            mbar_wait(mbD + 8 * slot, (k / 3) & 1);
            fence_proxy_async_cta();
            const uint32_t s0 = A + slot * SLOT_B;
            tma_store2d(&tmZf, h * TCH, tCur * ROWS, s0 + 0 * CH_B);
            tma_store2d(&tmZv, h * TCH, tCur * ROWS, s0 + 1 * CH_B);
            tma_commit();

            // ---- next tile id needed before loading chunk k+2 at h==2 ----
            if (h == 2) {
                tNext = grid + (int)atomicAdd(&g_work, 1u);
                tileSeq[(j + 1) & 7] = tNext;
            }

            // ---- load chunk k+2 (slot freed once store(k-1) drained) ----
            const int k2 = k + 2;
            const int s2 = k2 % 3;
            const int h2 = k2 & 3;
            const int t2 = (h < 2) ? tCur : tNext;
            if (t2 < ntiles) {
                tma_wait_read1();            // all but newest group drained
                const uint32_t d0 = A + s2 * SLOT_B;
                mbar_expect(mbF + 8 * s2, SLOT_B);
                tma_load2d(d0 + 0 * CH_B, &tmS, h2 * TCH, t2 * ROWS, mbF + 8 * s2);
                tma_load2d(d0 + 1 * CH_B, &tmC, h2 * TCH, t2 * ROWS, mbF + 8 * s2);
                tma_load2d(d0 + 2 * CH_B, &tmY, h2 * TCH, t2 * ROWS, mbF + 8 * s2);
            } else if (h2 == 0) {
                // first chunk of invalid tile: single wake so the consumer can
                // read tileSeq and exit
                mbar_arrive(mbF + 8 * s2);
            }

            if (h == 3) {
                if (tNext >= ntiles) break;  // last valid chunk stored above
                tCur = tNext;
                j++;
            }
            k++;
        }
        tma_wait_read0();    // drain final stores before smem death
        return;
    }

    // =====================================================================
    // Consumer: warp 0 (32 threads, one row each)
    // =====================================================================

    // ---- scalar params ----
    const float psi  = __ldg(p_psi);
    const float gS   = __ldg(p_gS);
    const float gC   = __ldg(p_gC);
    const float gG   = __ldg(p_gG);
    const float gGS  = __ldg(p_gGS);
    const float gGC  = __ldg(p_gGC);
    const float lsz  = __ldg(p_lsz);
    const float b0   = __ldg(p_b0);
    const float bZ   = __ldg(p_bZ);
    const float bS   = __ldg(p_bS);
    const float bG   = __ldg(p_bG);
    const float bGS  = __ldg(p_bGS);
    const float gw0  = __ldg(p_gLw + 0), gw1 = __ldg(p_gLw + 1), gw2 = __ldg(p_gLw + 2);
    const float bw0  = __ldg(p_bLw + 0), bw1 = __ldg(p_bLw + 1), bw2 = __ldg(p_bLw + 2);

    const float sz     = expf(lsz);
    const float sigma2 = sz * sz;
    const float psi2   = psi * psi;
    const float bZ2    = bZ * bZ;

#define STEP(s_, c_, y_, zf_, zv_)                                              \
        {                                                                       \
            float Zpred = fmaf(psi, Zm, fmaf(tS, (s_), fmaf(tC, (c_), tc0)));   \
            float Zpv   = fmaf(psi2, Zr, sigma2);                               \
            float logit = fmaf(bZ, Zpred, fmaf(oS, (s_), ob0));                 \
            logit = fminf(fmaxf(logit, -20.0f), 20.0f);                         \
            float e  = __expf(-logit);                                          \
            float p  = __fdividef(1.0f, 1.0f + e);                              \
            float pq = e * p * p;              /* p*(1-p) */                    \
            float hess = fmaf(bZ2, pq, 1e-6f);                                  \
            float Zpo  = __fdividef(Zpv, fmaf(Zpv, hess, 1.0f));                \
            float grad = ((y_) - p) * bZ;                                       \
            Zm = fmaf(Zpo, grad, Zpred);                                        \
            Zr = Zpo;                                                           \
            float sel = ((y_) != 0.0f) ? p : (1.0f - p);                        \
            llt += __logf(sel + 1e-10f);                                        \
            (zf_) = Zm;                                                         \
            (zv_) = Zr;                                                         \
        }

    // SW64 addressing in float4 units: idx = 4*r + (q ^ ((r>>1)&3)), r = tid.
    const int rb4 = tid * 4;
    const int rx  = (tid >> 1) & 3;

    int j = 0;
    int k = 0;

    #pragma unroll 1
    while (true) {
        // wait first chunk of tile j (gates tileSeq visibility)
        mbar_wait(mbF + 8 * (k % 3), (k / 3) & 1);
        const int t = (j == 0) ? bid : tileSeq[j & 7];
        if (t >= ntiles) break;

        // ---- per-tile row constants ----
        const int row = t * ROWS + tid;
        const float lw = (row < N) ? 1.0f : 0.0f;
        const int rr = (row < N) ? row : 0;
        const float Gn = __ldg(G + rr);
        const float l0 = __ldg(L + 3 * (size_t)rr + 0);
        const float l1 = __ldg(L + 3 * (size_t)rr + 1);
        const float l2 = __ldg(L + 3 * (size_t)rr + 2);
        const float gL = fmaf(gw0, l0, fmaf(gw1, l1, gw2 * l2));
        const float bL = fmaf(bw0, l0, fmaf(bw1, l1, bw2 * l2));
        const float tc0 = fmaf(gG, Gn, gL);
        const float tS  = fmaf(gGS, Gn, gS);
        const float tC  = fmaf(gGC, Gn, gC);
        const float ob0 = fmaf(bG, Gn, b0) + bL;
        const float oS  = fmaf(bGS, Gn, bS);

        float Zm = 0.0f, Zr = 1.0f, llt = 0.0f;

        #pragma unroll
        for (int h = 0; h < NCHT; h++) {
            const int slot = k % 3;
            if (h > 0) mbar_wait(mbF + 8 * slot, (k / 3) & 1);

            float4* const cS = (float4*)(Ag + slot * SLOT_B);
            float4* const cC = (float4*)(Ag + slot * SLOT_B + CH_B);
            float4* const cY = (float4*)(Ag + slot * SLOT_B + 2 * CH_B);
            #pragma unroll
            for (int q = 0; q < 4; q++) {
                const int idx = rb4 + (q ^ rx);
                const float4 s4 = cS[idx];
                const float4 c4 = cC[idx];
                const float4 y4 = cY[idx];
                float4 zf4, zv4;
                STEP(s4.x, c4.x, y4.x, zf4.x, zv4.x);
                STEP(s4.y, c4.y, y4.y, zf4.y, zv4.y);
                STEP(s4.z, c4.z, y4.z, zf4.z, zv4.z);
                STEP(s4.w, c4.w, y4.w, zf4.w, zv4.w);
                cS[idx] = zf4;   // Zf overwrites S slot
                cC[idx] = zv4;   // Zv overwrites C slot
            }
            mbar_arrive(mbD + 8 * slot);   // release: outputs visible to producer
            k++;
        }

        // ---- per-tile deterministic ll (single-warp reduce) ----
        float v = lw * llt;
        #pragma unroll
        for (int off = 16; off > 0; off >>= 1)
            v += __shfl_down_sync(0xffffffffu, v, off);
        if (lane == 0)
            g_tilell[t] = (double)v;

        j++;
    }
#undef STEP

    // ---- finish ticket; last CTA's consumer warp reduces tiles in order ----
    __syncwarp();
    if (tid == 0) {
        __threadfence();
        unsigned int ticket = atomicAdd(&g_ticket, 1u);
        is_last = (ticket == (unsigned)grid - 1);
        if (is_last) { g_ticket = 0; g_work = 0; }   // reset for graph replays
    }
    __syncwarp();

    if (is_last) {
        __threadfence();
        double s = 0.0;
        for (int i = tid; i < ntiles; i += CTHREADS)
            s += g_tilell[i];
        #pragma unroll
        for (int off = 16; off > 0; off >>= 1)
            s += __shfl_down_sync(0xffffffffu, s, off);
        if (tid == 0) *out_ll = (float)s;
    }
}

// ---------------- host side ----------------
typedef CUresult (*EncFn)(CUtensorMap*, CUtensorMapDataType, cuuint32_t, void*,
                          const cuuint64_t*, const cuuint64_t*, const cuuint32_t*,
                          const cuuint32_t*, CUtensorMapInterleave, CUtensorMapSwizzle,
                          CUtensorMapL2promotion, CUtensorMapFloatOOBfill);

static EncFn get_encoder()
{
    void* fp = nullptr;
    cudaDriverEntryPointQueryResult st;
#if CUDART_VERSION >= 12050
    cudaGetDriverEntryPointByVersion("cuTensorMapEncodeTiled", &fp, 12000,
                                     cudaEnableDefault, &st);
#else
    cudaGetDriverEntryPoint("cuTensorMapEncodeTiled", &fp, cudaEnableDefault, &st);
#endif
    return (EncFn)fp;
}

static void make_map(EncFn enc, CUtensorMap* m, const void* base, int N)
{
    cuuint64_t dims[2]    = {(cuuint64_t)T_STEPS, (cuuint64_t)N};
    cuuint64_t strides[1] = {(cuuint64_t)T_STEPS * 4};
    cuuint32_t box[2]     = {(cuuint32_t)TCH, (cuuint32_t)ROWS};   // 64B x 32 rows
    cuuint32_t es[2]      = {1u, 1u};
    enc(m, CU_TENSOR_MAP_DATA_TYPE_FLOAT32, 2, (void*)base,
        dims, strides, box, es,
        CU_TENSOR_MAP_INTERLEAVE_NONE, CU_TENSOR_MAP_SWIZZLE_64B,
        CU_TENSOR_MAP_L2_PROMOTION_L2_128B, CU_TENSOR_MAP_FLOAT_OOB_FILL_NONE);
}

extern "C" void kernel_launch(void* const* d_in, const int* in_sizes, int n_in,
                              void* d_out, int out_size)
{
    const float* G   = (const float*)d_in[0];
    const float* S   = (const float*)d_in[1];
    const float* C   = (const float*)d_in[2];
    const float* Y   = (const float*)d_in[3];
    const float* L   = (const float*)d_in[4];
    const float* psi = (const float*)d_in[5];
    const float* gS  = (const float*)d_in[6];
    const float* gC  = (const float*)d_in[7];
    const float* gG  = (const float*)d_in[8];
    const float* gGS = (const float*)d_in[9];
    const float* gGC = (const float*)d_in[10];
    const float* gLw = (const float*)d_in[11];
    const float* lsz = (const float*)d_in[12];
    const float* b0  = (const float*)d_in[13];
    const float* bZ  = (const float*)d_in[14];
    const float* bS  = (const float*)d_in[15];
    const float* bG  = (const float*)d_in[16];
    const float* bGS = (const float*)d_in[17];
    const float* bLw = (const float*)d_in[18];

    const int N = in_sizes[0];
    const size_t NT = (size_t)N * T_STEPS;

    float* out = (float*)d_out;
    float* Zf  = out;
    float* Zv  = out + NT;
    float* llp = out + 2 * NT;

    EncFn enc = get_encoder();
    CUtensorMap tmS, tmC, tmY, tmZf, tmZv;
    make_map(enc, &tmS,  S,  N);
    make_map(enc, &tmC,  C,  N);
    make_map(enc, &tmY,  Y,  N);
    make_map(enc, &tmZf, Zf, N);
    make_map(enc, &tmZv, Zv, N);

    cudaFuncSetAttribute(hmm_filter_ws10,
                         cudaFuncAttributeMaxDynamicSharedMemorySize, SMEM_DYN);

    const int ntiles = (N + ROWS - 1) / ROWS;
    const int blocks = (ntiles < NUM_CTAS) ? ntiles : NUM_CTAS;

    hmm_filter_ws10<<<blocks, THREADS, SMEM_DYN>>>(
        tmS, tmC, tmY, tmZf, tmZv,
        G, L,
        psi, gS, gC, gG, gGS, gGC, gLw, lsz,
        b0, bZ, bS, bG, bGS, bLw,
        llp, N, ntiles);
}

// round 16
// speedup vs baseline: 1.1425x; 1.1425x over previous
#include <cuda_runtime.h>
#include <cuda.h>
#include <math.h>
#include <stdint.h>

#define T_STEPS   64
#define ROWS      64             // rows per tile (= compute threads)
#define CTHREADS  64             // compute threads (warps 0,1)
#define THREADS   96             // + producer warp (warp 2)
#define TCH       16             // timesteps per chunk (64B per row)
#define NCHT      4              // chunks per tile
#define DEPTH     3              // ring slots; slot = k % 3
#define CH_B      (ROWS * TCH * 4)       // 4096 bytes per array per chunk
#define SLOT_B    (3 * CH_B)             // 12288: S+C+Y per slot
#define SMEM_DYN  (512 + DEPTH * SLOT_B + 64)   // ~37.4 KB -> 6 CTAs/SM
#define NUM_CTAS  888            // 6 * 148 SMs
#define MAXTILES  8192

// Deterministic per-TILE ll partials + self-resetting counters.
__device__ double       g_tilell[MAXTILES];
__device__ unsigned int g_work;
__device__ unsigned int g_ticket;

// ---------------- PTX helpers ----------------
__device__ __forceinline__ void mbar_init(uint32_t a, uint32_t cnt) {
    asm volatile("mbarrier.init.shared.b64 [%0], %1;" :: "r"(a), "r"(cnt) : "memory");
}
__device__ __forceinline__ void mbar_expect(uint32_t a, uint32_t bytes) {
    asm volatile("mbarrier.arrive.expect_tx.shared.b64 _, [%0], %1;"
                 :: "r"(a), "r"(bytes) : "memory");
}
__device__ __forceinline__ void mbar_arrive(uint32_t a) {
    asm volatile("mbarrier.arrive.shared.b64 _, [%0];" :: "r"(a) : "memory");
}
__device__ __forceinline__ void mbar_wait(uint32_t a, uint32_t parity) {
    uint32_t done;
    asm volatile(
        "{\n\t.reg .pred p;\n\t"
        "mbarrier.try_wait.parity.acquire.cta.shared::cta.b64 p, [%1], %2;\n\t"
        "selp.b32 %0, 1, 0, p;\n\t}"
        : "=r"(done) : "r"(a), "r"(parity) : "memory");
    if (!done) {
        asm volatile(
            "{\n\t.reg .pred P1;\n\t"
            "W_%=:\n\t"
            "mbarrier.try_wait.parity.acquire.cta.shared::cta.b64 P1, [%0], %1, 0x989680;\n\t"
            "@P1 bra.uni D_%=;\n\t"
            "bra.uni W_%=;\n\t"
            "D_%=:\n\t}" :: "r"(a), "r"(parity) : "memory");
    }
}
__device__ __forceinline__ void tma_load2d(uint32_t dst, const CUtensorMap* m,
                                           int c0, int c1, uint32_t mb) {
    asm volatile(
        "cp.async.bulk.tensor.2d.shared::cta.global.tile.mbarrier::complete_tx::bytes "
        "[%0], [%1, {%2, %3}], [%4];"
        :: "r"(dst), "l"(m), "r"(c0), "r"(c1), "r"(mb) : "memory");
}
__device__ __forceinline__ void tma_store2d(const CUtensorMap* m, int c0, int c1,
                                            uint32_t src) {
    asm volatile(
        "cp.async.bulk.tensor.2d.global.shared::cta.tile.bulk_group "
        "[%0, {%1, %2}], [%3];"
        :: "l"(m), "r"(c0), "r"(c1), "r"(src) : "memory");
}
__device__ __forceinline__ void fence_proxy_async_cta() {
    asm volatile("fence.proxy.async.shared::cta;" ::: "memory");
}
__device__ __forceinline__ void tma_commit() {
    asm volatile("cp.async.bulk.commit_group;" ::: "memory");
}
__device__ __forceinline__ void tma_wait_read1() {
    asm volatile("cp.async.bulk.wait_group.read 1;" ::: "memory");
}
__device__ __forceinline__ void tma_wait_read0() {
    asm volatile("cp.async.bulk.wait_group.read 0;" ::: "memory");
}

__global__ __launch_bounds__(THREADS)
void hmm_filter_ws6(
    const __grid_constant__ CUtensorMap tmS,
    const __grid_constant__ CUtensorMap tmC,
    const __grid_constant__ CUtensorMap tmY,
    const __grid_constant__ CUtensorMap tmZf,
    const __grid_constant__ CUtensorMap tmZv,
    const float* __restrict__ G,   // (N,1)
    const float* __restrict__ L,   // (N,3)
    const float* __restrict__ p_psi,
    const float* __restrict__ p_gS,
    const float* __restrict__ p_gC,
    const float* __restrict__ p_gG,
    const float* __restrict__ p_gGS,
    const float* __restrict__ p_gGC,
    const float* __restrict__ p_gLw,
    const float* __restrict__ p_lsz,
    const float* __restrict__ p_b0,
    const float* __restrict__ p_bZ,
    const float* __restrict__ p_bS,
    const float* __restrict__ p_bG,
    const float* __restrict__ p_bGS,
    const float* __restrict__ p_bLw,
    float* __restrict__ out_ll,
    int N, int ntiles)
{
    extern __shared__ char dsm[];
    __shared__ float  wsum[2];
    __shared__ double dsum[2];
    __shared__ int    tileSeq[8];
    __shared__ bool   is_last;

    const uint32_t sb = (uint32_t)__cvta_generic_to_shared(dsm);
    const uint32_t A  = (sb + 511u) & ~511u;     // 512B align (SW64 atom)
    char* const Ag    = dsm + (A - sb);

    // slot s: S at +0, C at +CH_B, Y at +2*CH_B within slot s*SLOT_B
    const uint32_t mbF = A + DEPTH * SLOT_B;        // full[3]
    const uint32_t mbD = mbF + 8 * DEPTH;           // done[3]

    const int tid  = threadIdx.x;
    const int lane = tid & 31;
    const int wid  = tid >> 5;
    const int bid  = blockIdx.x;
    const int grid = gridDim.x;

    if (tid == 0) {
        #pragma unroll
        for (int s = 0; s < DEPTH; s++) {
            mbar_init(mbF + 8 * s, 1);        // full: expect_tx / wake
            mbar_init(mbD + 8 * s, CTHREADS); // done: 64 compute arrivals
        }
    }
    __syncthreads();

    // =====================================================================
    // Producer: warp 2, lane 0 (other lanes exit)
    // =====================================================================
    if (wid == 2) {
        if (lane != 0) return;

        int tCur  = bid;          // grid <= ntiles guaranteed by host
        int tNext = -1;
        int j = 0;
        int k = 0;

        // Prologue: load chunks 0,1 (slots 0,1) of first tile
        #pragma unroll
        for (int kk = 0; kk < 2; kk++) {
            const uint32_t s0 = A + kk * SLOT_B;
            mbar_expect(mbF + 8 * kk, SLOT_B);
            tma_load2d(s0 + 0 * CH_B, &tmS, kk * TCH, tCur * ROWS, mbF + 8 * kk);
            tma_load2d(s0 + 1 * CH_B, &tmC, kk * TCH, tCur * ROWS, mbF + 8 * kk);
            tma_load2d(s0 + 2 * CH_B, &tmY, kk * TCH, tCur * ROWS, mbF + 8 * kk);
        }

        #pragma unroll 1
        while (true) {
            const int h    = k & 3;
            const int slot = k % 3;

            // ---- store chunk k once compute finished it ----
            mbar_wait(mbD + 8 * slot, (k / 3) & 1);
            fence_proxy_async_cta();
            const uint32_t s0 = A + slot * SLOT_B;
            tma_store2d(&tmZf, h * TCH, tCur * ROWS, s0 + 0 * CH_B);
            tma_store2d(&tmZv, h * TCH, tCur * ROWS, s0 + 1 * CH_B);
            tma_commit();

            // ---- next tile id needed before loading chunk k+2 at h==2 ----
            if (h == 2) {
                tNext = grid + (int)atomicAdd(&g_work, 1u);
                tileSeq[(j + 1) & 7] = tNext;
            }

            // ---- load chunk k+2 (slot freed once store(k-1) drained) ----
            const int k2 = k + 2;
            const int s2 = k2 % 3;
            const int h2 = k2 & 3;
            const int t2 = (h < 2) ? tCur : tNext;
            if (t2 < ntiles) {
                tma_wait_read1();            // all but newest group drained
                const uint32_t d0 = A + s2 * SLOT_B;
                mbar_expect(mbF + 8 * s2, SLOT_B);
                tma_load2d(d0 + 0 * CH_B, &tmS, h2 * TCH, t2 * ROWS, mbF + 8 * s2);
                tma_load2d(d0 + 1 * CH_B, &tmC, h2 * TCH, t2 * ROWS, mbF + 8 * s2);
                tma_load2d(d0 + 2 * CH_B, &tmY, h2 * TCH, t2 * ROWS, mbF + 8 * s2);
            } else if (h2 == 0) {
                // first chunk of invalid tile: single wake so consumers can
                // read tileSeq and exit
                mbar_arrive(mbF + 8 * s2);
            }

            if (h == 3) {
                if (tNext >= ntiles) break;  // last valid chunk stored above
                tCur = tNext;
                j++;
            }
            k++;
        }
        tma_wait_read0();    // drain final stores before smem death
        return;
    }

    // =====================================================================
    // Consumers: warps 0,1 (64 threads, one row each)
    // =====================================================================

    // ---- scalar params ----
    const float psi  = __ldg(p_psi);
    const float gS   = __ldg(p_gS);
    const float gC   = __ldg(p_gC);
    const float gG   = __ldg(p_gG);
    const float gGS  = __ldg(p_gGS);
    const float gGC  = __ldg(p_gGC);
    const float lsz  = __ldg(p_lsz);
    const float b0   = __ldg(p_b0);
    const float bZ   = __ldg(p_bZ);
    const float bS   = __ldg(p_bS);
    const float bG   = __ldg(p_bG);
    const float bGS  = __ldg(p_bGS);
    const float gw0  = __ldg(p_gLw + 0), gw1 = __ldg(p_gLw + 1), gw2 = __ldg(p_gLw + 2);
    const float bw0  = __ldg(p_bLw + 0), bw1 = __ldg(p_bLw + 1), bw2 = __ldg(p_bLw + 2);

    const float sz     = expf(lsz);
    const float sigma2 = sz * sz;
    const float psi2   = psi * psi;
    const float bZ2    = bZ * bZ;

#define STEP(s_, c_, y_, zf_, zv_)                                              \
        {                                                                       \
            float Zpred = fmaf(psi, Zm, fmaf(tS, (s_), fmaf(tC, (c_), tc0)));   \
            float Zpv   = fmaf(psi2, Zr, sigma2);                               \
            float logit = fmaf(bZ, Zpred, fmaf(oS, (s_), ob0));                 \
            logit = fminf(fmaxf(logit, -20.0f), 20.0f);                         \
            float e  = __expf(-logit);                                          \
            float p  = __fdividef(1.0f, 1.0f + e);                              \
            float pq = e * p * p;              /* p*(1-p) */                    \
            float hess = fmaf(bZ2, pq, 1e-6f);                                  \
            float Zpo  = __fdividef(Zpv, fmaf(Zpv, hess, 1.0f));                \
            float grad = ((y_) - p) * bZ;                                       \
            Zm = fmaf(Zpo, grad, Zpred);                                        \
            Zr = Zpo;                                                           \
            float sel = ((y_) != 0.0f) ? p : (1.0f - p);                        \
            llt += __logf(sel + 1e-10f);                                        \
            (zf_) = Zm;                                                         \
            (zv_) = Zr;                                                         \
        }

    // SW64 addressing in float4 units: idx = 4*r + (q ^ ((r>>1)&3)), r = tid.
    const int rb4 = tid * 4;
    const int rx  = (tid >> 1) & 3;

    int j = 0;
    int k = 0;

    #pragma unroll 1
    while (true) {
        // wait first chunk of tile j (gates tileSeq visibility)
        mbar_wait(mbF + 8 * (k % 3), (k / 3) & 1);
        const int t = (j == 0) ? bid : tileSeq[j & 7];
        if (t >= ntiles) break;

        // ---- per-tile row constants ----
        const int row = t * ROWS + tid;
        const float lw = (row < N) ? 1.0f : 0.0f;
        const int rr = (row < N) ? row : 0;
        const float Gn = __ldg(G + rr);
        const float l0 = __ldg(L + 3 * (size_t)rr + 0);
        const float l1 = __ldg(L + 3 * (size_t)rr + 1);
        const float l2 = __ldg(L + 3 * (size_t)rr + 2);
        const float gL = fmaf(gw0, l0, fmaf(gw1, l1, gw2 * l2));
        const float bL = fmaf(bw0, l0, fmaf(bw1, l1, bw2 * l2));
        const float tc0 = fmaf(gG, Gn, gL);
        const float tS  = fmaf(gGS, Gn, gS);
        const float tC  = fmaf(gGC, Gn, gC);
        const float ob0 = fmaf(bG, Gn, b0) + bL;
        const float oS  = fmaf(bGS, Gn, bS);

        float Zm = 0.0f, Zr = 1.0f, llt = 0.0f;

        #pragma unroll
        for (int h = 0; h < NCHT; h++) {
            const int slot = k % 3;
            if (h > 0) mbar_wait(mbF + 8 * slot, (k / 3) & 1);

            float4* const cS = (float4*)(Ag + slot * SLOT_B);
            float4* const cC = (float4*)(Ag + slot * SLOT_B + CH_B);
            float4* const cY = (float4*)(Ag + slot * SLOT_B + 2 * CH_B);
            #pragma unroll
            for (int q = 0; q < 4; q++) {
                const int idx = rb4 + (q ^ rx);
                const float4 s4 = cS[idx];
                const float4 c4 = cC[idx];
                const float4 y4 = cY[idx];
                float4 zf4, zv4;
                STEP(s4.x, c4.x, y4.x, zf4.x, zv4.x);
                STEP(s4.y, c4.y, y4.y, zf4.y, zv4.y);
                STEP(s4.z, c4.z, y4.z, zf4.z, zv4.z);
                STEP(s4.w, c4.w, y4.w, zf4.w, zv4.w);
                cS[idx] = zf4;   // Zf overwrites S slot
                cC[idx] = zv4;   // Zv overwrites C slot
            }
            mbar_arrive(mbD + 8 * slot);   // release: outputs visible to producer
            k++;
        }

        // ---- per-tile deterministic ll ----
        float v = lw * llt;
        #pragma unroll
        for (int off = 16; off > 0; off >>= 1)
            v += __shfl_down_sync(0xffffffffu, v, off);
        if (lane == 0) wsum[wid] = v;
        asm volatile("bar.sync 1, 64;" ::: "memory");
        if (tid == 0)
            g_tilell[t] = (double)(wsum[0] + wsum[1]);

        j++;
    }
#undef STEP

    // ---- finish ticket; last CTA reduces tiles in fixed order ----
    asm volatile("bar.sync 1, 64;" ::: "memory");
    if (tid == 0) {
        __threadfence();
        unsigned int ticket = atomicAdd(&g_ticket, 1u);
        is_last = (ticket == (unsigned)grid - 1);
        if (is_last) { g_ticket = 0; g_work = 0; }   // reset for graph replays
    }
    asm volatile("bar.sync 1, 64;" ::: "memory");

    if (is_last) {
        __threadfence();
        double s = 0.0;
        for (int i = tid; i < ntiles; i += CTHREADS)
            s += g_tilell[i];
        #pragma unroll
        for (int off = 16; off > 0; off >>= 1)
            s += __shfl_down_sync(0xffffffffu, s, off);
        if (lane == 0) dsum[wid] = s;
        asm volatile("bar.sync 1, 64;" ::: "memory");
        if (tid == 0) *out_ll = (float)(dsum[0] + dsum[1]);
    }
}

// ---------------- host side ----------------
typedef CUresult (*EncFn)(CUtensorMap*, CUtensorMapDataType, cuuint32_t, void*,
                          const cuuint64_t*, const cuuint64_t*, const cuuint32_t*,
                          const cuuint32_t*, CUtensorMapInterleave, CUtensorMapSwizzle,
                          CUtensorMapL2promotion, CUtensorMapFloatOOBfill);

static EncFn get_encoder()
{
    void* fp = nullptr;
    cudaDriverEntryPointQueryResult st;
#if CUDART_VERSION >= 12050
    cudaGetDriverEntryPointByVersion("cuTensorMapEncodeTiled", &fp, 12000,
                                     cudaEnableDefault, &st);
#else
    cudaGetDriverEntryPoint("cuTensorMapEncodeTiled", &fp, cudaEnableDefault, &st);
#endif
    return (EncFn)fp;
}

static void make_map(EncFn enc, CUtensorMap* m, const void* base, int N,
                     CUtensorMapL2promotion promo)
{
    cuuint64_t dims[2]    = {(cuuint64_t)T_STEPS, (cuuint64_t)N};
    cuuint64_t strides[1] = {(cuuint64_t)T_STEPS * 4};
    cuuint32_t box[2]     = {(cuuint32_t)TCH, (cuuint32_t)ROWS};   // 64B x 64 rows
    cuuint32_t es[2]      = {1u, 1u};
    enc(m, CU_TENSOR_MAP_DATA_TYPE_FLOAT32, 2, (void*)base,
        dims, strides, box, es,
        CU_TENSOR_MAP_INTERLEAVE_NONE, CU_TENSOR_MAP_SWIZZLE_64B,
        promo, CU_TENSOR_MAP_FLOAT_OOB_FILL_NONE);
}

extern "C" void kernel_launch(void* const* d_in, const int* in_sizes, int n_in,
                              void* d_out, int out_size)
{
    const float* G   = (const float*)d_in[0];
    const float* S   = (const float*)d_in[1];
    const float* C   = (const float*)d_in[2];
    const float* Y   = (const float*)d_in[3];
    const float* L   = (const float*)d_in[4];
    const float* psi = (const float*)d_in[5];
    const float* gS  = (const float*)d_in[6];
    const float* gC  = (const float*)d_in[7];
    const float* gG  = (const float*)d_in[8];
    const float* gGS = (const float*)d_in[9];
    const float* gGC = (const float*)d_in[10];
    const float* gLw = (const float*)d_in[11];
    const float* lsz = (const float*)d_in[12];
    const float* b0  = (const float*)d_in[13];
    const float* bZ  = (const float*)d_in[14];
    const float* bS  = (const float*)d_in[15];
    const float* bG  = (const float*)d_in[16];
    const float* bGS = (const float*)d_in[17];
    const float* bLw = (const float*)d_in[18];

    const int N = in_sizes[0];
    const size_t NT = (size_t)N * T_STEPS;

    float* out = (float*)d_out;
    float* Zf  = out;
    float* Zv  = out + NT;
    float* llp = out + 2 * NT;

    EncFn enc = get_encoder();
    CUtensorMap tmS, tmC, tmY, tmZf, tmZv;
    // Loads: promote to 256B so chunk 0 of a tile pulls the whole 256B row
    // into L2 and chunks 1-3 hit L2 instead of DRAM.
    make_map(enc, &tmS,  S,  N, CU_TENSOR_MAP_L2_PROMOTION_L2_256B);
    make_map(enc, &tmC,  C,  N, CU_TENSOR_MAP_L2_PROMOTION_L2_256B);
    make_map(enc, &tmY,  Y,  N, CU_TENSOR_MAP_L2_PROMOTION_L2_256B);
    // Stores: keep 128B promotion.
    make_map(enc, &tmZf, Zf, N, CU_TENSOR_MAP_L2_PROMOTION_L2_128B);
    make_map(enc, &tmZv, Zv, N, CU_TENSOR_MAP_L2_PROMOTION_L2_128B);

    cudaFuncSetAttribute(hmm_filter_ws6,
                         cudaFuncAttributeMaxDynamicSharedMemorySize, SMEM_DYN);

    const int ntiles = (N + ROWS - 1) / ROWS;
    const int blocks = (ntiles < NUM_CTAS) ? ntiles : NUM_CTAS;

    hmm_filter_ws6<<<blocks, THREADS, SMEM_DYN>>>(
        tmS, tmC, tmY, tmZf, tmZv,
        G, L,
        psi, gS, gC, gG, gGS, gGC, gLw, lsz,
        b0, bZ, bS, bG, bGS, bLw,
        llp, N, ntiles);
}

// round 17
// speedup vs baseline: 1.2388x; 1.0843x over previous
#include <cuda_runtime.h>
#include <cuda.h>
#include <math.h>
#include <stdint.h>

#define T_STEPS   64
#define ROWS      64             // rows per tile (= compute threads)
#define CTHREADS  64             // compute threads (warps 0,1)
#define THREADS   96             // + producer warp (warp 2)
#define TCH       16             // timesteps per chunk (64B per row)
#define NCHT      4              // chunks per tile
#define DEPTH     3              // ring slots; slot = k % 3
#define CH_B      (ROWS * TCH * 4)       // 4096 bytes per array per chunk
#define SLOT_B    (3 * CH_B)             // 12288: S+C+Y per slot
#define SMEM_DYN  (512 + DEPTH * SLOT_B + 64)   // ~37.4 KB -> 6 CTAs/SM
#define NUM_CTAS  888            // 6 * 148 SMs
#define MAXTILES  8192

// Deterministic per-TILE ll partials + self-resetting counters.
__device__ double       g_tilell[MAXTILES];
__device__ unsigned int g_work;
__device__ unsigned int g_ticket;

// ---------------- PTX helpers ----------------
__device__ __forceinline__ void mbar_init(uint32_t a, uint32_t cnt) {
    asm volatile("mbarrier.init.shared.b64 [%0], %1;" :: "r"(a), "r"(cnt) : "memory");
}
__device__ __forceinline__ void mbar_expect(uint32_t a, uint32_t bytes) {
    asm volatile("mbarrier.arrive.expect_tx.shared.b64 _, [%0], %1;"
                 :: "r"(a), "r"(bytes) : "memory");
}
__device__ __forceinline__ void mbar_arrive(uint32_t a) {
    asm volatile("mbarrier.arrive.shared.b64 _, [%0];" :: "r"(a) : "memory");
}
__device__ __forceinline__ void mbar_wait(uint32_t a, uint32_t parity) {
    uint32_t done;
    asm volatile(
        "{\n\t.reg .pred p;\n\t"
        "mbarrier.try_wait.parity.acquire.cta.shared::cta.b64 p, [%1], %2;\n\t"
        "selp.b32 %0, 1, 0, p;\n\t}"
        : "=r"(done) : "r"(a), "r"(parity) : "memory");
    if (!done) {
        asm volatile(
            "{\n\t.reg .pred P1;\n\t"
            "W_%=:\n\t"
            "mbarrier.try_wait.parity.acquire.cta.shared::cta.b64 P1, [%0], %1, 0x989680;\n\t"
            "@P1 bra.uni D_%=;\n\t"
            "bra.uni W_%=;\n\t"
            "D_%=:\n\t}" :: "r"(a), "r"(parity) : "memory");
    }
}
__device__ __forceinline__ void tma_load2d(uint32_t dst, const CUtensorMap* m,
                                           int c0, int c1, uint32_t mb) {
    asm volatile(
        "cp.async.bulk.tensor.2d.shared::cta.global.tile.mbarrier::complete_tx::bytes "
        "[%0], [%1, {%2, %3}], [%4];"
        :: "r"(dst), "l"(m), "r"(c0), "r"(c1), "r"(mb) : "memory");
}
__device__ __forceinline__ void tma_store2d(const CUtensorMap* m, int c0, int c1,
                                            uint32_t src) {
    asm volatile(
        "cp.async.bulk.tensor.2d.global.shared::cta.tile.bulk_group "
        "[%0, {%1, %2}], [%3];"
        :: "l"(m), "r"(c0), "r"(c1), "r"(src) : "memory");
}
__device__ __forceinline__ void fence_proxy_async_cta() {
    asm volatile("fence.proxy.async.shared::cta;" ::: "memory");
}
__device__ __forceinline__ void tma_commit() {
    asm volatile("cp.async.bulk.commit_group;" ::: "memory");
}
__device__ __forceinline__ void tma_wait_read1() {
    asm volatile("cp.async.bulk.wait_group.read 1;" ::: "memory");
}
__device__ __forceinline__ void tma_wait_read0() {
    asm volatile("cp.async.bulk.wait_group.read 0;" ::: "memory");
}

__global__ __launch_bounds__(THREADS)
void hmm_filter_ws6b(
    const __grid_constant__ CUtensorMap tmS,
    const __grid_constant__ CUtensorMap tmC,
    const __grid_constant__ CUtensorMap tmY,
    const __grid_constant__ CUtensorMap tmZf,
    const __grid_constant__ CUtensorMap tmZv,
    const float* __restrict__ G,   // (N,1)
    const float* __restrict__ L,   // (N,3)
    const float* __restrict__ p_psi,
    const float* __restrict__ p_gS,
    const float* __restrict__ p_gC,
    const float* __restrict__ p_gG,
    const float* __restrict__ p_gGS,
    const float* __restrict__ p_gGC,
    const float* __restrict__ p_gLw,
    const float* __restrict__ p_lsz,
    const float* __restrict__ p_b0,
    const float* __restrict__ p_bZ,
    const float* __restrict__ p_bS,
    const float* __restrict__ p_bG,
    const float* __restrict__ p_bGS,
    const float* __restrict__ p_bLw,
    float* __restrict__ out_ll,
    int N, int ntiles)
{
    extern __shared__ char dsm[];
    __shared__ float  wsum[2];
    __shared__ double dsum[2];
    __shared__ int    tileSeq[8];
    __shared__ bool   is_last;

    const uint32_t sb = (uint32_t)__cvta_generic_to_shared(dsm);
    const uint32_t A  = (sb + 511u) & ~511u;     // 512B align (SW64 atom)
    char* const Ag    = dsm + (A - sb);

    // slot s: S at +0, C at +CH_B, Y at +2*CH_B within slot s*SLOT_B
    const uint32_t mbF = A + DEPTH * SLOT_B;        // full[3]
    const uint32_t mbD = mbF + 8 * DEPTH;           // done[3]

    const int tid  = threadIdx.x;
    const int lane = tid & 31;
    const int wid  = tid >> 5;
    const int bid  = blockIdx.x;
    const int grid = gridDim.x;

    if (tid == 0) {
        #pragma unroll
        for (int s = 0; s < DEPTH; s++) {
            mbar_init(mbF + 8 * s, 1);        // full: expect_tx / wake
            mbar_init(mbD + 8 * s, CTHREADS); // done: 64 compute arrivals
        }
    }
    __syncthreads();

    // =====================================================================
    // Producer: warp 2, lane 0 (other lanes exit)
    // =====================================================================
    if (wid == 2) {
        if (lane != 0) return;

        int tCur  = bid;          // grid <= ntiles guaranteed by host
        int tNext = -1;
        int j = 0;
        int k = 0;

        // Prologue: load chunks 0,1 (slots 0,1) of first tile
        #pragma unroll
        for (int kk = 0; kk < 2; kk++) {
            const uint32_t s0 = A + kk * SLOT_B;
            mbar_expect(mbF + 8 * kk, SLOT_B);
            tma_load2d(s0 + 0 * CH_B, &tmS, kk * TCH, tCur * ROWS, mbF + 8 * kk);
            tma_load2d(s0 + 1 * CH_B, &tmC, kk * TCH, tCur * ROWS, mbF + 8 * kk);
            tma_load2d(s0 + 2 * CH_B, &tmY, kk * TCH, tCur * ROWS, mbF + 8 * kk);
        }

        #pragma unroll 1
        while (true) {
            const int h    = k & 3;
            const int slot = k % 3;

            // ---- store chunk k once compute finished it ----
            mbar_wait(mbD + 8 * slot, (k / 3) & 1);
            fence_proxy_async_cta();
            const uint32_t s0 = A + slot * SLOT_B;
            tma_store2d(&tmZf, h * TCH, tCur * ROWS, s0 + 0 * CH_B);
            tma_store2d(&tmZv, h * TCH, tCur * ROWS, s0 + 1 * CH_B);
            tma_commit();

            // ---- next tile id needed before loading chunk k+2 at h==2 ----
            if (h == 2) {
                tNext = grid + (int)atomicAdd(&g_work, 1u);
                tileSeq[(j + 1) & 7] = tNext;
            }

            // ---- load chunk k+2 (slot freed once store(k-1) drained) ----
            const int k2 = k + 2;
            const int s2 = k2 % 3;
            const int h2 = k2 & 3;
            const int t2 = (h < 2) ? tCur : tNext;
            if (t2 < ntiles) {
                tma_wait_read1();            // all but newest group drained
                const uint32_t d0 = A + s2 * SLOT_B;
                mbar_expect(mbF + 8 * s2, SLOT_B);
                tma_load2d(d0 + 0 * CH_B, &tmS, h2 * TCH, t2 * ROWS, mbF + 8 * s2);
                tma_load2d(d0 + 1 * CH_B, &tmC, h2 * TCH, t2 * ROWS, mbF + 8 * s2);
                tma_load2d(d0 + 2 * CH_B, &tmY, h2 * TCH, t2 * ROWS, mbF + 8 * s2);
            } else if (h2 == 0) {
                // first chunk of invalid tile: single wake so consumers can
                // read tileSeq and exit
                mbar_arrive(mbF + 8 * s2);
            }

            if (h == 3) {
                if (tNext >= ntiles) break;  // last valid chunk stored above
                tCur = tNext;
                j++;
            }
            k++;
        }
        tma_wait_read0();    // drain final stores before smem death
        return;
    }

    // =====================================================================
    // Consumers: warps 0,1 (64 threads, one row each)
    // =====================================================================

    // ---- scalar params ----
    const float psi  = __ldg(p_psi);
    const float gS   = __ldg(p_gS);
    const float gC   = __ldg(p_gC);
    const float gG   = __ldg(p_gG);
    const float gGS  = __ldg(p_gGS);
    const float gGC  = __ldg(p_gGC);
    const float lsz  = __ldg(p_lsz);
    const float b0   = __ldg(p_b0);
    const float bZ   = __ldg(p_bZ);
    const float bS   = __ldg(p_bS);
    const float bG   = __ldg(p_bG);
    const float bGS  = __ldg(p_bGS);
    const float gw0  = __ldg(p_gLw + 0), gw1 = __ldg(p_gLw + 1), gw2 = __ldg(p_gLw + 2);
    const float bw0  = __ldg(p_bLw + 0), bw1 = __ldg(p_bLw + 1), bw2 = __ldg(p_bLw + 2);

    const float sz     = expf(lsz);
    const float sigma2 = sz * sz;
    const float psi2   = psi * psi;
    const float bZ2    = bZ * bZ;

// STEP: identical filter math; ll contribution accumulated as a PRODUCT
// (pr_ *= sel+eps), one __logf per 4 steps. sel+eps in (1e-10, 1+1e-10];
// realistic sel >= sigmoid(-20) ~ 2e-9, so products of 4 stay normal-range.
#define STEP(s_, c_, y_, zf_, zv_, pr_)                                         \
        {                                                                       \
            float Zpred = fmaf(psi, Zm, fmaf(tS, (s_), fmaf(tC, (c_), tc0)));   \
            float Zpv   = fmaf(psi2, Zr, sigma2);                               \
            float logit = fmaf(bZ, Zpred, fmaf(oS, (s_), ob0));                 \
            logit = fminf(fmaxf(logit, -20.0f), 20.0f);                         \
            float e  = __expf(-logit);                                          \
            float p  = __fdividef(1.0f, 1.0f + e);                              \
            float pq = e * p * p;              /* p*(1-p) */                    \
            float hess = fmaf(bZ2, pq, 1e-6f);                                  \
            float Zpo  = __fdividef(Zpv, fmaf(Zpv, hess, 1.0f));                \
            float grad = ((y_) - p) * bZ;                                       \
            Zm = fmaf(Zpo, grad, Zpred);                                        \
            Zr = Zpo;                                                           \
            float sel = ((y_) != 0.0f) ? p : (1.0f - p);                        \
            (pr_) *= (sel + 1e-10f);                                            \
            (zf_) = Zm;                                                         \
            (zv_) = Zr;                                                         \
        }

    // SW64 addressing in float4 units: idx = 4*r + (q ^ ((r>>1)&3)), r = tid.
    const int rb4 = tid * 4;
    const int rx  = (tid >> 1) & 3;

    int j = 0;
    int k = 0;

    #pragma unroll 1
    while (true) {
        // wait first chunk of tile j (gates tileSeq visibility)
        mbar_wait(mbF + 8 * (k % 3), (k / 3) & 1);
        const int t = (j == 0) ? bid : tileSeq[j & 7];
        if (t >= ntiles) break;

        // ---- per-tile row constants ----
        const int row = t * ROWS + tid;
        const float lw = (row < N) ? 1.0f : 0.0f;
        const int rr = (row < N) ? row : 0;
        const float Gn = __ldg(G + rr);
        const float l0 = __ldg(L + 3 * (size_t)rr + 0);
        const float l1 = __ldg(L + 3 * (size_t)rr + 1);
        const float l2 = __ldg(L + 3 * (size_t)rr + 2);
        const float gL = fmaf(gw0, l0, fmaf(gw1, l1, gw2 * l2));
        const float bL = fmaf(bw0, l0, fmaf(bw1, l1, bw2 * l2));
        const float tc0 = fmaf(gG, Gn, gL);
        const float tS  = fmaf(gGS, Gn, gS);
        const float tC  = fmaf(gGC, Gn, gC);
        const float ob0 = fmaf(bG, Gn, b0) + bL;
        const float oS  = fmaf(bGS, Gn, bS);

        float Zm = 0.0f, Zr = 1.0f, llt = 0.0f;

        #pragma unroll
        for (int h = 0; h < NCHT; h++) {
            const int slot = k % 3;
            if (h > 0) mbar_wait(mbF + 8 * slot, (k / 3) & 1);

            float4* const cS = (float4*)(Ag + slot * SLOT_B);
            float4* const cC = (float4*)(Ag + slot * SLOT_B + CH_B);
            float4* const cY = (float4*)(Ag + slot * SLOT_B + 2 * CH_B);
            #pragma unroll
            for (int q = 0; q < 4; q++) {
                const int idx = rb4 + (q ^ rx);
                const float4 s4 = cS[idx];
                const float4 c4 = cC[idx];
                const float4 y4 = cY[idx];
                float4 zf4, zv4;
                float pr = 1.0f;
                STEP(s4.x, c4.x, y4.x, zf4.x, zv4.x, pr);
                STEP(s4.y, c4.y, y4.y, zf4.y, zv4.y, pr);
                STEP(s4.z, c4.z, y4.z, zf4.z, zv4.z, pr);
                STEP(s4.w, c4.w, y4.w, zf4.w, zv4.w, pr);
                llt += __logf(pr);   // one LG2 per 4 steps
                cS[idx] = zf4;   // Zf overwrites S slot
                cC[idx] = zv4;   // Zv overwrites C slot
            }
            mbar_arrive(mbD + 8 * slot);   // release: outputs visible to producer
            k++;
        }

        // ---- per-tile deterministic ll ----
        float v = lw * llt;
        #pragma unroll
        for (int off = 16; off > 0; off >>= 1)
            v += __shfl_down_sync(0xffffffffu, v, off);
        if (lane == 0) wsum[wid] = v;
        asm volatile("bar.sync 1, 64;" ::: "memory");
        if (tid == 0)
            g_tilell[t] = (double)(wsum[0] + wsum[1]);

        j++;
    }
#undef STEP

    // ---- finish ticket; last CTA reduces tiles in fixed order ----
    asm volatile("bar.sync 1, 64;" ::: "memory");
    if (tid == 0) {
        __threadfence();
        unsigned int ticket = atomicAdd(&g_ticket, 1u);
        is_last = (ticket == (unsigned)grid - 1);
        if (is_last) { g_ticket = 0; g_work = 0; }   // reset for graph replays
    }
    asm volatile("bar.sync 1, 64;" ::: "memory");

    if (is_last) {
        __threadfence();
        double s = 0.0;
        for (int i = tid; i < ntiles; i += CTHREADS)
            s += g_tilell[i];
        #pragma unroll
        for (int off = 16; off > 0; off >>= 1)
            s += __shfl_down_sync(0xffffffffu, s, off);
        if (lane == 0) dsum[wid] = s;
        asm volatile("bar.sync 1, 64;" ::: "memory");
        if (tid == 0) *out_ll = (float)(dsum[0] + dsum[1]);
    }
}

// ---------------- host side ----------------
typedef CUresult (*EncFn)(CUtensorMap*, CUtensorMapDataType, cuuint32_t, void*,
                          const cuuint64_t*, const cuuint64_t*, const cuuint32_t*,
                          const cuuint32_t*, CUtensorMapInterleave, CUtensorMapSwizzle,
                          CUtensorMapL2promotion, CUtensorMapFloatOOBfill);

static EncFn get_encoder()
{
    void* fp = nullptr;
    cudaDriverEntryPointQueryResult st;
#if CUDART_VERSION >= 12050
    cudaGetDriverEntryPointByVersion("cuTensorMapEncodeTiled", &fp, 12000,
                                     cudaEnableDefault, &st);
#else
    cudaGetDriverEntryPoint("cuTensorMapEncodeTiled", &fp, cudaEnableDefault, &st);
#endif
    return (EncFn)fp;
}

static void make_map(EncFn enc, CUtensorMap* m, const void* base, int N)
{
    cuuint64_t dims[2]    = {(cuuint64_t)T_STEPS, (cuuint64_t)N};
    cuuint64_t strides[1] = {(cuuint64_t)T_STEPS * 4};
    cuuint32_t box[2]     = {(cuuint32_t)TCH, (cuuint32_t)ROWS};   // 64B x 64 rows
    cuuint32_t es[2]      = {1u, 1u};
    enc(m, CU_TENSOR_MAP_DATA_TYPE_FLOAT32, 2, (void*)base,
        dims, strides, box, es,
        CU_TENSOR_MAP_INTERLEAVE_NONE, CU_TENSOR_MAP_SWIZZLE_64B,
        CU_TENSOR_MAP_L2_PROMOTION_L2_128B, CU_TENSOR_MAP_FLOAT_OOB_FILL_NONE);
}

extern "C" void kernel_launch(void* const* d_in, const int* in_sizes, int n_in,
                              void* d_out, int out_size)
{
    const float* G   = (const float*)d_in[0];
    const float* S   = (const float*)d_in[1];
    const float* C   = (const float*)d_in[2];
    const float* Y   = (const float*)d_in[3];
    const float* L   = (const float*)d_in[4];
    const float* psi = (const float*)d_in[5];
    const float* gS  = (const float*)d_in[6];
    const float* gC  = (const float*)d_in[7];
    const float* gG  = (const float*)d_in[8];
    const float* gGS = (const float*)d_in[9];
    const float* gGC = (const float*)d_in[10];
    const float* gLw = (const float*)d_in[11];
    const float* lsz = (const float*)d_in[12];
    const float* b0  = (const float*)d_in[13];
    const float* bZ  = (const float*)d_in[14];
    const float* bS  = (const float*)d_in[15];
    const float* bG  = (const float*)d_in[16];
    const float* bGS = (const float*)d_in[17];
    const float* bLw = (const float*)d_in[18];

    const int N = in_sizes[0];
    const size_t NT = (size_t)N * T_STEPS;

    float* out = (float*)d_out;
    float* Zf  = out;
    float* Zv  = out + NT;
    float* llp = out + 2 * NT;

    EncFn enc = get_encoder();
    CUtensorMap tmS, tmC, tmY, tmZf, tmZv;
    make_map(enc, &tmS,  S,  N);
    make_map(enc, &tmC,  C,  N);
    make_map(enc, &tmY,  Y,  N);
    make_map(enc, &tmZf, Zf, N);
    make_map(enc, &tmZv, Zv, N);

    cudaFuncSetAttribute(hmm_filter_ws6b,
                         cudaFuncAttributeMaxDynamicSharedMemorySize, SMEM_DYN);

    const int ntiles = (N + ROWS - 1) / ROWS;
    const int blocks = (ntiles < NUM_CTAS) ? ntiles : NUM_CTAS;

    hmm_filter_ws6b<<<blocks, THREADS, SMEM_DYN>>>(
        tmS, tmC, tmY, tmZf, tmZv,
        G, L,
        psi, gS, gC, gG, gGS, gGC, gLw, lsz,
        b0, bZ, bS, bG, bGS, bLw,
        llp, N, ntiles);
}